// round 13
// baseline (speedup 1.0000x reference)
#include <cuda_runtime.h>
#include <cuda_fp16.h>
#include <math.h>
#include <stdint.h>

// Problem constants
#define BATCH   2
#define NSEQ    32768          // H*W*D
#define NC      256
#define NHEADS  8
#define DH      32
#define NROWS   (BATCH*NSEQ)   // 65536
#define FFDIM   1024
#define LN_EPS  1e-3f
#define NSPLIT  32

// ---------------- scratch (static __device__, no allocation) ----------------
__device__ __half g_Qp[(size_t)NROWS * NC];
__device__ __half g_Kp[(size_t)NROWS * NC];
__device__ __half g_Vp[(size_t)NROWS * NC];
__device__ float  g_partmax[(BATCH * (NSEQ/256)) * NC];
__device__ float  g_colmax[BATCH * NC];
__device__ float  g_Spart[(size_t)BATCH * NHEADS * NSPLIT * DH * DH];
__device__ float  g_Zpart[(size_t)BATCH * NHEADS * NSPLIT * DH];
__device__ float  g_ctx[BATCH * NHEADS * DH * DH];

__device__ __half g_qh [(size_t)NROWS * NC];
__device__ __half g_kvh[(size_t)NROWS * NC];
__device__ __half g_xh [(size_t)NROWS * NC];
__device__ __half g_hh [(size_t)NROWS * FFDIM];
__device__ __half g_wqT [NC*NC];
__device__ __half g_wkvT[2*NC*NC];      // K rows [0,256), V rows [256,512)
__device__ __half g_f1T[FFDIM*NC];
__device__ __half g_f2T[NC*FFDIM];

// ======================= PTX helpers =======================================
__device__ __forceinline__ uint32_t smem_u32(const void* p) {
    uint32_t a;
    asm("{ .reg .u64 t; cvta.to.shared.u64 t, %1; cvt.u32.u64 %0, t; }" : "=r"(a) : "l"(p));
    return a;
}
__device__ __forceinline__ void ldsm4(uint32_t* r, uint32_t addr) {
    asm volatile("ldmatrix.sync.aligned.m8n8.x4.shared.b16 {%0,%1,%2,%3}, [%4];"
        : "=r"(r[0]), "=r"(r[1]), "=r"(r[2]), "=r"(r[3]) : "r"(addr));
}
__device__ __forceinline__ void mma16816(float* c, const uint32_t* a, const uint32_t* b) {
    asm volatile("mma.sync.aligned.m16n8k16.row.col.f32.f16.f16.f32 "
        "{%0,%1,%2,%3}, {%4,%5,%6,%7}, {%8,%9}, {%0,%1,%2,%3};"
        : "+f"(c[0]), "+f"(c[1]), "+f"(c[2]), "+f"(c[3])
        : "r"(a[0]), "r"(a[1]), "r"(a[2]), "r"(a[3]), "r"(b[0]), "r"(b[1]));
}
#define CP16(dst, src) \
    asm volatile("cp.async.cg.shared.global [%0], [%1], 16;" :: "r"(dst), "l"(src))
#define CP_COMMIT()  asm volatile("cp.async.commit_group;" ::: "memory")
#define CP_WAIT2()   asm volatile("cp.async.wait_group 2;" ::: "memory")
#define CP_WAIT1()   asm volatile("cp.async.wait_group 1;" ::: "memory")
#define CP_WAIT0()   asm volatile("cp.async.wait_group 0;" ::: "memory")

__device__ __forceinline__ float gelu_exact(float v) {
    return 0.5f * v * (1.0f + erff(v * 0.70710678118654752440f));
}

// ======================= HMMA fp16 GEMM, 128x256 CTA tile ===================
// C[M,N] = A[M,K] @ W[K,N]; A fp16 [M][K]; W fp16 [N][K].
// 8 warps (2x4 of 64x64), k-chunk 64, 4-stage cp.async pipeline, 1 CTA/SM.
#define KCH    64
#define BSTRB  144
#define ATILEB (128*BSTRB)             // 18432
#define BTILEB (256*BSTRB)             // 36864
#define STAGEB (ATILEB+BTILEB)         // 55296
#define NSTAGE 4
#define GEMM_SMEM (NSTAGE*STAGEB)      // 221184

// 256 threads, ROWS rows x 64 halves
template<int ROWS>
__device__ __forceinline__ void load_tile(const __half* __restrict__ src,
                                          uint32_t dstbase, int row0, int col0,
                                          int ldk, int tid) {
    const __half* s = src + (size_t)(row0 + (tid >> 3)) * ldk + col0 + (tid & 7) * 8;
    uint32_t d = dstbase + (uint32_t)(tid >> 3) * BSTRB + (uint32_t)(tid & 7) * 16;
    #pragma unroll
    for (int p = 0; p < ROWS / 32; p++)
        CP16(d + p * 32 * BSTRB, s + (size_t)p * 32 * ldk);
}

// EPI 0: bias -> fp16.  EPI 1: bias+gelu -> fp16.  EPI 2: bias+resid+LN -> fp32.
// FUSE: grid.x selects (C,bias) for bx=0 and (C2,bias2) for bx=1, each 256 wide.
template<int EPI, int FUSE>
__global__ __launch_bounds__(256, 1)
void tc_gemm(const __half* __restrict__ A, const __half* __restrict__ B,
             const float* __restrict__ bias, const float* __restrict__ bias2,
             __half* __restrict__ C, __half* __restrict__ C2,
             const __half* __restrict__ resid,
             const float* __restrict__ lng, const float* __restrict__ lnb,
             float* __restrict__ outF,
             int N, int K) {
    extern __shared__ __align__(1024) char smem[];
    const uint32_t sb = smem_u32(smem);
    const int tid  = threadIdx.x;
    const int wid  = tid >> 5;
    const int lane = tid & 31;
    const int wm = wid & 1;            // 2 row groups of 64
    const int wn = wid >> 1;           // 4 col groups of 64
    const int rowA0 = blockIdx.y * 128;
    const int rowB0 = blockIdx.x * 256;
    const int nch = K / KCH;

    __half* Cout; const float* bi; int colbase, ldC;
    if (FUSE) {
        if (blockIdx.x == 0) { Cout = C;  bi = bias;  }
        else                 { Cout = C2; bi = bias2; }
        colbase = 0; ldC = 256;
    } else {
        Cout = C; bi = bias; colbase = blockIdx.x * 256; ldC = N;
    }

    const int row_a  = (lane & 7) + ((lane >> 3) & 1) * 8;
    const int kcol_a = (lane >> 4) * 8;
    const uint32_t aoff = (uint32_t)(wm * 64 + row_a) * BSTRB + kcol_a * 2;
    const int row_b  = (lane & 7) + (lane >> 4) * 8;
    const int kcol_b = ((lane >> 3) & 1) * 8;
    const uint32_t boff = (uint32_t)(wn * 64 + row_b) * BSTRB + kcol_b * 2;

    float c[4][8][4];
    #pragma unroll
    for (int i = 0; i < 4; i++)
        #pragma unroll
        for (int j = 0; j < 8; j++)
            #pragma unroll
            for (int q = 0; q < 4; q++) c[i][j][q] = 0.0f;

    // prologue: stages 0,1,2
    #pragma unroll
    for (int p = 0; p < 3; p++) {
        load_tile<128>(A, sb + p * STAGEB,          rowA0, p * KCH, K, tid);
        load_tile<256>(B, sb + p * STAGEB + ATILEB, rowB0, p * KCH, K, tid);
        CP_COMMIT();
    }

    for (int ch = 0; ch < nch; ch++) {
        const int s = ch & 3;
        if (ch + 2 < nch) CP_WAIT2();
        else if (ch + 1 < nch) CP_WAIT1();
        else CP_WAIT0();
        __syncthreads();
        if (ch + 3 < nch) {
            const int ns = (ch + 3) & 3;
            const int col0 = (ch + 3) * KCH;
            load_tile<128>(A, sb + ns * STAGEB,          rowA0, col0, K, tid);
            load_tile<256>(B, sb + ns * STAGEB + ATILEB, rowB0, col0, K, tid);
            CP_COMMIT();
        }

        const uint32_t aP = sb + s * STAGEB + aoff;
        const uint32_t bP = sb + s * STAGEB + ATILEB + boff;

        #pragma unroll
        for (int ks = 0; ks < KCH / 16; ks++) {
            uint32_t a[4][4], b[8][2];
            #pragma unroll
            for (int mt = 0; mt < 4; mt++)
                ldsm4(a[mt], aP + mt * 16 * BSTRB + ks * 32);
            #pragma unroll
            for (int nt2 = 0; nt2 < 4; nt2++) {
                uint32_t r[4];
                ldsm4(r, bP + nt2 * 16 * BSTRB + ks * 32);
                b[nt2 * 2 + 0][0] = r[0]; b[nt2 * 2 + 0][1] = r[1];
                b[nt2 * 2 + 1][0] = r[2]; b[nt2 * 2 + 1][1] = r[3];
            }
            #pragma unroll
            for (int mt = 0; mt < 4; mt++)
                #pragma unroll
                for (int nt = 0; nt < 8; nt++)
                    mma16816(c[mt][nt], a[mt], b[nt]);
        }
    }

    __syncthreads();   // tiles dead; smem reusable

    if (EPI == 2) {
        // fused bias + residual + LayerNorm -> fp32 out (CTA holds full rows)
        float* s1 = (float*)smem;          // [128][4]
        float* s2 = (float*)smem + 512;    // [128][4]
        #pragma unroll
        for (int mt = 0; mt < 4; mt++) {
            #pragma unroll
            for (int h = 0; h < 2; h++) {
                const int rloc = wm * 64 + mt * 16 + h * 8 + (lane >> 2);
                const int rowg = blockIdx.y * 128 + rloc;
                float ssum = 0.f, ssq = 0.f;
                #pragma unroll
                for (int nt = 0; nt < 8; nt++) {
                    const int colw = wn * 64 + nt * 8 + 2 * (lane & 3);
                    __half2 rr = *(const __half2*)(resid + (size_t)rowg * 256 + colw);
                    float v0 = c[mt][nt][h * 2 + 0] + bi[colw]     + __low2float(rr);
                    float v1 = c[mt][nt][h * 2 + 1] + bi[colw + 1] + __high2float(rr);
                    c[mt][nt][h * 2 + 0] = v0;
                    c[mt][nt][h * 2 + 1] = v1;
                    ssum += v0 + v1;
                    ssq  += v0 * v0 + v1 * v1;
                }
                ssum += __shfl_xor_sync(0xffffffffu, ssum, 1);
                ssq  += __shfl_xor_sync(0xffffffffu, ssq, 1);
                ssum += __shfl_xor_sync(0xffffffffu, ssum, 2);
                ssq  += __shfl_xor_sync(0xffffffffu, ssq, 2);
                if ((lane & 3) == 0) { s1[rloc * 4 + wn] = ssum; s2[rloc * 4 + wn] = ssq; }
            }
        }
        __syncthreads();
        #pragma unroll
        for (int mt = 0; mt < 4; mt++) {
            #pragma unroll
            for (int h = 0; h < 2; h++) {
                const int rloc = wm * 64 + mt * 16 + h * 8 + (lane >> 2);
                const int rowg = blockIdx.y * 128 + rloc;
                const float S = s1[rloc * 4 + 0] + s1[rloc * 4 + 1] + s1[rloc * 4 + 2] + s1[rloc * 4 + 3];
                const float Q = s2[rloc * 4 + 0] + s2[rloc * 4 + 1] + s2[rloc * 4 + 2] + s2[rloc * 4 + 3];
                const float mean = S * (1.0f / NC);
                const float var  = Q * (1.0f / NC) - mean * mean;
                const float rs   = rsqrtf(var + LN_EPS);
                #pragma unroll
                for (int nt = 0; nt < 8; nt++) {
                    const int colw = wn * 64 + nt * 8 + 2 * (lane & 3);
                    float o0 = (c[mt][nt][h * 2 + 0] - mean) * rs * lng[colw]     + lnb[colw];
                    float o1 = (c[mt][nt][h * 2 + 1] - mean) * rs * lng[colw + 1] + lnb[colw + 1];
                    *(float2*)(outF + (size_t)rowg * 256 + colw) = make_float2(o0, o1);
                }
            }
        }
        return;
    }

    // EPI 0/1: bias (+gelu) -> swizzled smem stage -> 128B coalesced rows
    char* wst = smem + wid * 8192;
    #pragma unroll
    for (int mt = 0; mt < 4; mt++) {
        #pragma unroll
        for (int nt = 0; nt < 8; nt++) {
            const int colw = nt * 8 + 2 * (lane & 3);
            const int colg = colbase + wn * 64 + colw;
            const float b0 = bi[colg], b1 = bi[colg + 1];
            #pragma unroll
            for (int h = 0; h < 2; h++) {
                const int rloc = mt * 16 + h * 8 + (lane >> 2);
                float v0 = c[mt][nt][h * 2 + 0] + b0;
                float v1 = c[mt][nt][h * 2 + 1] + b1;
                if (EPI == 1) { v0 = gelu_exact(v0); v1 = gelu_exact(v1); }
                __half2 p = __floats2half2_rn(v0, v1);
                uint32_t off = (uint32_t)rloc * 128 + colw * 2;
                off ^= ((off >> 3) & 0x70);
                *(uint32_t*)(wst + off) = *(uint32_t*)&p;
            }
        }
    }
    __syncwarp();
    const int rowg0 = blockIdx.y * 128 + wm * 64;
    const int colg0 = colbase + wn * 64;
    #pragma unroll
    for (int p = 0; p < 16; p++) {
        const int rloc = p * 4 + (lane >> 3);
        const int ch8  = lane & 7;
        uint32_t off = (uint32_t)rloc * 128 + (uint32_t)((ch8 ^ (rloc & 7)) * 16);
        uint4 val = *(uint4*)(wst + off);
        *(uint4*)(Cout + (size_t)(rowg0 + rloc) * ldC + colg0 + ch8 * 8) = val;
    }
}

// ======================= conversion kernels =================================
__global__ void conv_half2_kernel(const float* __restrict__ x0, __half* __restrict__ d0,
                                  const float* __restrict__ x1, __half* __restrict__ d1) {
    size_t gi = (size_t)blockIdx.x * blockDim.x + threadIdx.x;
    const float* x; __half* d;
    size_t n4 = (size_t)NROWS * NC / 4;
    if (gi < n4) { x = x0; d = d0; }
    else { x = x1; d = d1; gi -= n4; }
    size_t i = gi * 4;
    float4 v = *(const float4*)(x + i);
    __half2 a = __floats2half2_rn(v.x, v.y);
    __half2 b = __floats2half2_rn(v.z, v.w);
    *(uint2*)(d + i) = make_uint2(*(uint32_t*)&a, *(uint32_t*)&b);
}

__global__ void convT_all_kernel(const float* wq, const float* wk, const float* wv,
                                 const float* f1, const float* f2,
                                 __half* tq, __half* tk, __half* tv,
                                 __half* t1, __half* t2) {
    __shared__ float t[32][33];
    int b = blockIdx.x;
    const float* W; __half* T; int K, N;
    if      (b < 64)  { W = wq; T = tq; K = NC;    N = NC;    }
    else if (b < 128) { W = wk; T = tk; K = NC;    N = NC;    b -= 64;  }
    else if (b < 192) { W = wv; T = tv; K = NC;    N = NC;    b -= 128; }
    else if (b < 448) { W = f1; T = t1; K = NC;    N = FFDIM; b -= 192; }
    else              { W = f2; T = t2; K = FFDIM; N = NC;    b -= 448; }
    const int nx = N / 32;
    const int n0 = (b % nx) * 32, k0 = (b / nx) * 32;
    const int tx = threadIdx.x, ty = threadIdx.y;
    for (int i = ty; i < 32; i += 8) t[i][tx] = W[(size_t)(k0 + i) * N + n0 + tx];
    __syncthreads();
    for (int i = ty; i < 32; i += 8)
        T[(size_t)(n0 + i) * K + k0 + tx] = __float2half_rn(t[tx][i]);
}

// ======================= attention middle ===================================
__global__ void colmax_part_kernel() {
    const int chunk = blockIdx.x;
    const int b = chunk / (NSEQ / 256);
    const int r0 = (chunk % (NSEQ / 256)) * 256;
    const int c = threadIdx.x;
    const __half* base = g_Kp + ((size_t)b * NSEQ + r0) * NC;
    float m = -INFINITY;
    for (int r = 0; r < 256; r++)
        m = fmaxf(m, __half2float(base[(size_t)r * NC + c]));
    g_partmax[(size_t)chunk * NC + c] = m;
}
__global__ void colmax_red_kernel() {
    const int b = blockIdx.x;
    const int c = threadIdx.x;
    float m = -INFINITY;
    for (int ch = 0; ch < NSEQ / 256; ch++)
        m = fmaxf(m, g_partmax[((size_t)(b * (NSEQ / 256) + ch)) * NC + c]);
    g_colmax[b * NC + c] = m;
}

#define CGRP 32
__global__ __launch_bounds__(256)
void ctx_part_kernel() {
    const int s  = blockIdx.x;
    const int bh = blockIdx.y;
    const int b = bh / NHEADS;
    const int h = bh % NHEADS;
    const int t = threadIdx.x;
    const int chunk = NSEQ / NSPLIT;
    __shared__ float ek[CGRP][DH];
    __shared__ float vv[CGRP][DH];
    const int e  = t & 31;
    const int d0 = (t >> 5) * 4;
    float acc0 = 0.f, acc1 = 0.f, acc2 = 0.f, acc3 = 0.f, zacc = 0.f;
    for (int g = 0; g < chunk / CGRP; g++) {
        #pragma unroll
        for (int i = 0; i < CGRP * 2 * DH / 256; i++) {
            int idx = t + i * 256;
            int row = idx >> 6;
            int col = idx & 63;
            int n = s * chunk + g * CGRP + row;
            size_t base = ((size_t)b * NSEQ + n) * NC + h * DH;
            if (col < DH) {
                float kv = __half2float(g_Kp[base + col]);
                ek[row][col] = expf(kv - g_colmax[b * NC + h * DH + col]);
            } else {
                vv[row][col - DH] = __half2float(g_Vp[base + (col - DH)]);
            }
        }
        __syncthreads();
        #pragma unroll 8
        for (int row = 0; row < CGRP; row++) {
            float v = vv[row][e];
            acc0 = fmaf(ek[row][d0 + 0], v, acc0);
            acc1 = fmaf(ek[row][d0 + 1], v, acc1);
            acc2 = fmaf(ek[row][d0 + 2], v, acc2);
            acc3 = fmaf(ek[row][d0 + 3], v, acc3);
        }
        if (t < DH) {
            #pragma unroll 8
            for (int row = 0; row < CGRP; row++) zacc += ek[row][t];
        }
        __syncthreads();
    }
    const size_t sp = ((size_t)bh * NSPLIT + s) * (DH * DH);
    g_Spart[sp + (d0 + 0) * DH + e] = acc0;
    g_Spart[sp + (d0 + 1) * DH + e] = acc1;
    g_Spart[sp + (d0 + 2) * DH + e] = acc2;
    g_Spart[sp + (d0 + 3) * DH + e] = acc3;
    if (t < DH) g_Zpart[((size_t)bh * NSPLIT + s) * DH + t] = zacc;
}
__global__ void ctx_reduce_kernel() {
    const int bh = blockIdx.x;
    const int t = threadIdx.x;
    const int d = t >> 5;
    __shared__ float zs[DH];
    float ssum = 0.f;
    for (int p = 0; p < NSPLIT; p++)
        ssum += g_Spart[((size_t)bh * NSPLIT + p) * (DH * DH) + t];
    if (t < DH) {
        float z = 0.f;
        for (int p = 0; p < NSPLIT; p++)
            z += g_Zpart[((size_t)bh * NSPLIT + p) * DH + t];
        zs[t] = z;
    }
    __syncthreads();
    g_ctx[(size_t)bh * (DH * DH) + t] = ssum / zs[d];
}

// fused softmax(Q) -> attn -> +residual -> LN1; two-phase, 1 barrier/block
#define ROWS_PER_BLK 16
__global__ __launch_bounds__(256)
void attn_ln1_kernel(const float* __restrict__ gamma,
                     const float* __restrict__ beta) {
    __shared__ float ys[ROWS_PER_BLK][NC];
    __shared__ float gb[2][NC];
    const int t = threadIdx.x;
    const int h = t >> 5;
    const int lane = t & 31;
    const int row0 = blockIdx.x * ROWS_PER_BLK;
    const int b = row0 / NSEQ;

    float ctx[DH];
    const float* cb = g_ctx + ((size_t)b * NHEADS + h) * DH * DH;
    #pragma unroll
    for (int d = 0; d < DH; d++) ctx[d] = cb[d * DH + lane];
    gb[0][t] = gamma[t];
    gb[1][t] = beta[t];

    for (int r = 0; r < ROWS_PER_BLK; r++) {
        const size_t off = (size_t)(row0 + r) * NC;
        float qv = __half2float(g_Qp[off + t]);
        float m = qv;
        #pragma unroll
        for (int s = 16; s > 0; s >>= 1) m = fmaxf(m, __shfl_xor_sync(0xffffffffu, m, s));
        float ev = expf(qv - m);
        float ss = ev;
        #pragma unroll
        for (int s = 16; s > 0; s >>= 1) ss += __shfl_xor_sync(0xffffffffu, ss, s);
        float qn = ev / ss;
        float acc = 0.f;
        #pragma unroll
        for (int d = 0; d < DH; d++) {
            float qd = __shfl_sync(0xffffffffu, qn, d);
            acc = fmaf(qd, ctx[d], acc);
        }
        ys[r][t] = __half2float(g_qh[off + t]) + acc;
    }
    __syncthreads();

    #pragma unroll
    for (int rr = 0; rr < ROWS_PER_BLK / 8; rr++) {
        const int r = h * (ROWS_PER_BLK / 8) + rr;
        float v[8], s1 = 0.f, s2 = 0.f;
        #pragma unroll
        for (int j = 0; j < 8; j++) {
            v[j] = ys[r][lane + 32 * j];
            s1 += v[j];
            s2 += v[j] * v[j];
        }
        #pragma unroll
        for (int s = 16; s > 0; s >>= 1) {
            s1 += __shfl_xor_sync(0xffffffffu, s1, s);
            s2 += __shfl_xor_sync(0xffffffffu, s2, s);
        }
        const float mean = s1 * (1.0f / NC);
        const float var  = s2 * (1.0f / NC) - mean * mean;
        const float rs   = rsqrtf(var + LN_EPS);
        const size_t off = (size_t)(row0 + r) * NC;
        #pragma unroll
        for (int j = 0; j < 8; j++) {
            const int c = lane + 32 * j;
            float xv = (v[j] - mean) * rs * gb[0][c] + gb[1][c];
            g_xh[off + c] = __float2half_rn(xv);
        }
    }
}

// ======================= launch =============================================
extern "C" void kernel_launch(void* const* d_in, const int* in_sizes, int n_in,
                              void* d_out, int out_size) {
    const float* q     = (const float*)d_in[0];
    const float* kv    = (const float*)d_in[1];
    const float* wq_w  = (const float*)d_in[2];
    const float* wq_b  = (const float*)d_in[3];
    const float* wk_w  = (const float*)d_in[4];
    const float* wk_b  = (const float*)d_in[5];
    const float* wv_w  = (const float*)d_in[6];
    const float* wv_b  = (const float*)d_in[7];
    const float* ln1_g = (const float*)d_in[8];
    const float* ln1_b = (const float*)d_in[9];
    const float* ff1_w = (const float*)d_in[10];
    const float* ff1_b = (const float*)d_in[11];
    const float* ff2_w = (const float*)d_in[12];
    const float* ff2_b = (const float*)d_in[13];
    const float* ln2_g = (const float*)d_in[14];
    const float* ln2_b = (const float*)d_in[15];
    float* out = (float*)d_out;

    void *pQ, *pK, *pV;
    void *pqh, *pkvh, *pxh, *phh;
    void *wq, *wkv, *f1, *f2;
    cudaGetSymbolAddress(&pQ, g_Qp);    cudaGetSymbolAddress(&pK, g_Kp);
    cudaGetSymbolAddress(&pV, g_Vp);
    cudaGetSymbolAddress(&pqh, g_qh);   cudaGetSymbolAddress(&pkvh, g_kvh);
    cudaGetSymbolAddress(&pxh, g_xh);   cudaGetSymbolAddress(&phh, g_hh);
    cudaGetSymbolAddress(&wq, g_wqT);   cudaGetSymbolAddress(&wkv, g_wkvT);
    cudaGetSymbolAddress(&f1, g_f1T);   cudaGetSymbolAddress(&f2, g_f2T);

    cudaFuncSetAttribute(tc_gemm<0,0>, cudaFuncAttributeMaxDynamicSharedMemorySize, GEMM_SMEM);
    cudaFuncSetAttribute(tc_gemm<0,1>, cudaFuncAttributeMaxDynamicSharedMemorySize, GEMM_SMEM);
    cudaFuncSetAttribute(tc_gemm<1,0>, cudaFuncAttributeMaxDynamicSharedMemorySize, GEMM_SMEM);
    cudaFuncSetAttribute(tc_gemm<2,0>, cudaFuncAttributeMaxDynamicSharedMemorySize, GEMM_SMEM);

    const size_t n4 = (size_t)NROWS * NC / 4;
    conv_half2_kernel<<<(int)(2 * n4 / 256), 256>>>(q, (__half*)pqh, kv, (__half*)pkvh);
    dim3 tb(32, 8);
    convT_all_kernel<<<704, tb>>>(wq_w, wk_w, wv_w, ff1_w, ff2_w,
                                  (__half*)wq, (__half*)wkv,
                                  (__half*)wkv + 256 * NC,
                                  (__half*)f1, (__half*)f2);

    // Q projection (full-width CTA) ; K+V fused: bx=0 -> K, bx=1 -> V
    dim3 gQ(1, NROWS / 128);
    tc_gemm<0,0><<<gQ, 256, GEMM_SMEM>>>((__half*)pqh, (__half*)wq, wq_b, 0,
                                         (__half*)pQ, 0, 0, 0, 0, 0, NC, NC);
    dim3 gKV(2, NROWS / 128);
    tc_gemm<0,1><<<gKV, 256, GEMM_SMEM>>>((__half*)pkvh, (__half*)wkv, wk_b, wv_b,
                                          (__half*)pK, (__half*)pV, 0, 0, 0, 0, 512, NC);

    // attention middle
    colmax_part_kernel<<<BATCH * (NSEQ / 256), 256>>>();
    colmax_red_kernel<<<BATCH, 256>>>();
    ctx_part_kernel<<<dim3(NSPLIT, BATCH * NHEADS), 256>>>();
    ctx_reduce_kernel<<<BATCH * NHEADS, DH * DH>>>();
    attn_ln1_kernel<<<NROWS / ROWS_PER_BLK, 256>>>(ln1_g, ln1_b);

    // FF1 (gelu) ; FF2 fused with residual + LN2 -> out
    dim3 gFF1(FFDIM / 256, NROWS / 128);
    tc_gemm<1,0><<<gFF1, 256, GEMM_SMEM>>>((__half*)pxh, (__half*)f1, ff1_b, 0,
                                           (__half*)phh, 0, 0, 0, 0, 0, FFDIM, NC);
    dim3 gFF2(1, NROWS / 128);
    tc_gemm<2,0><<<gFF2, 256, GEMM_SMEM>>>((__half*)phh, (__half*)f2, ff2_b, 0,
                                           0, 0, (__half*)pxh, ln2_g, ln2_b, out,
                                           NC, FFDIM);
}

// round 14
// speedup vs baseline: 1.0639x; 1.0639x over previous
#include <cuda_runtime.h>
#include <cuda_fp16.h>
#include <math.h>
#include <stdint.h>

// Problem constants
#define BATCH   2
#define NSEQ    32768          // H*W*D
#define NC      256
#define NHEADS  8
#define DH      32
#define NROWS   (BATCH*NSEQ)   // 65536
#define FFDIM   1024
#define LN_EPS  1e-3f
#define NSPLIT  32

// ---------------- scratch (static __device__, no allocation) ----------------
__device__ __half g_Qp[(size_t)NROWS * NC];
__device__ __half g_Kp[(size_t)NROWS * NC];
__device__ __half g_Vp[(size_t)NROWS * NC];
__device__ __half g_ffout[(size_t)NROWS * NC];
__device__ float  g_partmax[(BATCH * (NSEQ/256)) * NC];
__device__ float  g_colmax[BATCH * NC];
__device__ float  g_Spart[(size_t)BATCH * NHEADS * NSPLIT * DH * DH];
__device__ float  g_Zpart[(size_t)BATCH * NHEADS * NSPLIT * DH];
__device__ float  g_ctx[BATCH * NHEADS * DH * DH];

__device__ __half g_qh [(size_t)NROWS * NC];
__device__ __half g_kvh[(size_t)NROWS * NC];
__device__ __half g_xh [(size_t)NROWS * NC];
__device__ __half g_hh [(size_t)NROWS * FFDIM];
__device__ __half g_wqT [NC*NC];
__device__ __half g_wkvT[2*NC*NC];      // K rows [0,256), V rows [256,512)
__device__ __half g_f1T[FFDIM*NC];
__device__ __half g_f2T[NC*FFDIM];

// ======================= PTX helpers =======================================
__device__ __forceinline__ uint32_t smem_u32(const void* p) {
    uint32_t a;
    asm("{ .reg .u64 t; cvta.to.shared.u64 t, %1; cvt.u32.u64 %0, t; }" : "=r"(a) : "l"(p));
    return a;
}
__device__ __forceinline__ void ldsm4(uint32_t* r, uint32_t addr) {
    asm volatile("ldmatrix.sync.aligned.m8n8.x4.shared.b16 {%0,%1,%2,%3}, [%4];"
        : "=r"(r[0]), "=r"(r[1]), "=r"(r[2]), "=r"(r[3]) : "r"(addr));
}
__device__ __forceinline__ void mma16816(float* c, const uint32_t* a, const uint32_t* b) {
    asm volatile("mma.sync.aligned.m16n8k16.row.col.f32.f16.f16.f32 "
        "{%0,%1,%2,%3}, {%4,%5,%6,%7}, {%8,%9}, {%0,%1,%2,%3};"
        : "+f"(c[0]), "+f"(c[1]), "+f"(c[2]), "+f"(c[3])
        : "r"(a[0]), "r"(a[1]), "r"(a[2]), "r"(a[3]), "r"(b[0]), "r"(b[1]));
}
#define CP16(dst, src) \
    asm volatile("cp.async.cg.shared.global [%0], [%1], 16;" :: "r"(dst), "l"(src))
#define CP_COMMIT()  asm volatile("cp.async.commit_group;" ::: "memory")
#define CP_WAIT1()   asm volatile("cp.async.wait_group 1;" ::: "memory")
#define CP_WAIT0()   asm volatile("cp.async.wait_group 0;" ::: "memory")

__device__ __forceinline__ float gelu_exact(float v) {
    return 0.5f * v * (1.0f + erff(v * 0.70710678118654752440f));
}

// ======================= HMMA fp16 GEMM (round-11 core: 128x128, 2 CTA/SM) ==
#define KCH   64
#define BSTR  72
#define BSTRB (BSTR*2)
#define TILEB (128*BSTRB)
#define NSTAGE 3
#define SOFF(s, t) (((s)*2 + (t)) * TILEB)
#define GEMM_SMEM (NSTAGE * 2 * TILEB) // 110592

__device__ __forceinline__ void load_tile(const __half* __restrict__ src,
                                          uint32_t dstbase, int row0, int col0,
                                          int ldk, int tid) {
    const __half* s = src + (size_t)(row0 + (tid >> 3)) * ldk + col0 + (tid & 7) * 8;
    uint32_t d = dstbase + (uint32_t)(tid >> 3) * BSTRB + (uint32_t)(tid & 7) * 16;
    #pragma unroll
    for (int p = 0; p < 8; p++)
        CP16(d + p * 16 * BSTRB, s + (size_t)p * 16 * ldk);
}

template<int EPI, int FUSE>
__global__ __launch_bounds__(128, 2)
void tc_gemm(const __half* __restrict__ A, const __half* __restrict__ B,
             const float* __restrict__ bias, const float* __restrict__ bias2,
             __half* __restrict__ C, __half* __restrict__ C2,
             int N, int K) {
    extern __shared__ __align__(1024) char smem[];
    const uint32_t sb = smem_u32(smem);
    const int tid  = threadIdx.x;
    const int wid  = tid >> 5;
    const int lane = tid & 31;
    const int wm = wid & 1;
    const int wn = wid >> 1;
    const int rowA0 = blockIdx.y * 128;
    const int rowB0 = blockIdx.x * 128;
    const int nch = K / KCH;

    __half* Cout; const float* bi; int colbase, ldC;
    if (FUSE) {
        int gc = blockIdx.x * 128;
        if (gc < 256) { Cout = C;  bi = bias;  colbase = gc; }
        else          { Cout = C2; bi = bias2; colbase = gc - 256; }
        ldC = 256;
    } else {
        Cout = C; bi = bias; colbase = blockIdx.x * 128; ldC = N;
    }

    const int row_a  = (lane & 7) + ((lane >> 3) & 1) * 8;
    const int kcol_a = (lane >> 4) * 8;
    const uint32_t aoff = (uint32_t)(wm * 64 + row_a) * BSTRB + kcol_a * 2;
    const int row_b  = (lane & 7) + (lane >> 4) * 8;
    const int kcol_b = ((lane >> 3) & 1) * 8;
    const uint32_t boff = (uint32_t)(wn * 64 + row_b) * BSTRB + kcol_b * 2;

    float c[4][8][4];
    #pragma unroll
    for (int i = 0; i < 4; i++)
        #pragma unroll
        for (int j = 0; j < 8; j++)
            #pragma unroll
            for (int q = 0; q < 4; q++) c[i][j][q] = 0.0f;

    load_tile(A, sb + SOFF(0, 0), rowA0, 0, K, tid);
    load_tile(B, sb + SOFF(0, 1), rowB0, 0, K, tid);
    CP_COMMIT();
    if (nch > 1) {
        load_tile(A, sb + SOFF(1, 0), rowA0, KCH, K, tid);
        load_tile(B, sb + SOFF(1, 1), rowB0, KCH, K, tid);
        CP_COMMIT();
    }

    for (int ch = 0; ch < nch; ch++) {
        const int s = ch % NSTAGE;
        if (ch + 1 < nch) CP_WAIT1(); else CP_WAIT0();
        __syncthreads();
        if (ch + 2 < nch) {
            const int ns = (ch + 2) % NSTAGE;
            const int col0 = (ch + 2) * KCH;
            load_tile(A, sb + SOFF(ns, 0), rowA0, col0, K, tid);
            load_tile(B, sb + SOFF(ns, 1), rowB0, col0, K, tid);
            CP_COMMIT();
        }

        const uint32_t aP = sb + SOFF(s, 0) + aoff;
        const uint32_t bP = sb + SOFF(s, 1) + boff;

        #pragma unroll
        for (int ks = 0; ks < KCH / 16; ks++) {
            uint32_t a[4][4], b[8][2];
            #pragma unroll
            for (int mt = 0; mt < 4; mt++)
                ldsm4(a[mt], aP + mt * 16 * BSTRB + ks * 32);
            #pragma unroll
            for (int nt2 = 0; nt2 < 4; nt2++) {
                uint32_t r[4];
                ldsm4(r, bP + nt2 * 16 * BSTRB + ks * 32);
                b[nt2 * 2 + 0][0] = r[0]; b[nt2 * 2 + 0][1] = r[1];
                b[nt2 * 2 + 1][0] = r[2]; b[nt2 * 2 + 1][1] = r[3];
            }
            #pragma unroll
            for (int mt = 0; mt < 4; mt++)
                #pragma unroll
                for (int nt = 0; nt < 8; nt++)
                    mma16816(c[mt][nt], a[mt], b[nt]);
        }
    }

    // epilogue: bias (+gelu) -> swizzled smem stage -> 128B coalesced rows
    __syncthreads();
    char* wst = smem + wid * 8192;
    #pragma unroll
    for (int mt = 0; mt < 4; mt++) {
        #pragma unroll
        for (int nt = 0; nt < 8; nt++) {
            const int colw = nt * 8 + 2 * (lane & 3);
            const int colg = colbase + wn * 64 + colw;
            const float b0 = bi[colg], b1 = bi[colg + 1];
            #pragma unroll
            for (int h = 0; h < 2; h++) {
                const int rloc = mt * 16 + h * 8 + (lane >> 2);
                float v0 = c[mt][nt][h * 2 + 0] + b0;
                float v1 = c[mt][nt][h * 2 + 1] + b1;
                if (EPI == 1) { v0 = gelu_exact(v0); v1 = gelu_exact(v1); }
                __half2 p = __floats2half2_rn(v0, v1);
                uint32_t off = (uint32_t)rloc * 128 + colw * 2;
                off ^= ((off >> 3) & 0x70);
                *(uint32_t*)(wst + off) = *(uint32_t*)&p;
            }
        }
    }
    __syncwarp();
    const int rowg0 = blockIdx.y * 128 + wm * 64;
    const int colg0 = colbase + wn * 64;
    #pragma unroll
    for (int p = 0; p < 16; p++) {
        const int rloc = p * 4 + (lane >> 3);
        const int ch8  = lane & 7;
        uint32_t off = (uint32_t)rloc * 128 + (uint32_t)((ch8 ^ (rloc & 7)) * 16);
        uint4 val = *(uint4*)(wst + off);
        *(uint4*)(Cout + (size_t)(rowg0 + rloc) * ldC + colg0 + ch8 * 8) = val;
    }
}

// ======================= conversion kernels =================================
__global__ void conv_half2_kernel(const float* __restrict__ x0, __half* __restrict__ d0,
                                  const float* __restrict__ x1, __half* __restrict__ d1) {
    size_t gi = (size_t)blockIdx.x * blockDim.x + threadIdx.x;
    const float* x; __half* d;
    size_t n4 = (size_t)NROWS * NC / 4;
    if (gi < n4) { x = x0; d = d0; }
    else { x = x1; d = d1; gi -= n4; }
    size_t i = gi * 4;
    float4 v = *(const float4*)(x + i);
    __half2 a = __floats2half2_rn(v.x, v.y);
    __half2 b = __floats2half2_rn(v.z, v.w);
    *(uint2*)(d + i) = make_uint2(*(uint32_t*)&a, *(uint32_t*)&b);
}

__global__ void convT_all_kernel(const float* wq, const float* wk, const float* wv,
                                 const float* f1, const float* f2,
                                 __half* tq, __half* tk, __half* tv,
                                 __half* t1, __half* t2) {
    __shared__ float t[32][33];
    int b = blockIdx.x;
    const float* W; __half* T; int K, N;
    if      (b < 64)  { W = wq; T = tq; K = NC;    N = NC;    }
    else if (b < 128) { W = wk; T = tk; K = NC;    N = NC;    b -= 64;  }
    else if (b < 192) { W = wv; T = tv; K = NC;    N = NC;    b -= 128; }
    else if (b < 448) { W = f1; T = t1; K = NC;    N = FFDIM; b -= 192; }
    else              { W = f2; T = t2; K = FFDIM; N = NC;    b -= 448; }
    const int nx = N / 32;
    const int n0 = (b % nx) * 32, k0 = (b / nx) * 32;
    const int tx = threadIdx.x, ty = threadIdx.y;
    for (int i = ty; i < 32; i += 8) t[i][tx] = W[(size_t)(k0 + i) * N + n0 + tx];
    __syncthreads();
    for (int i = ty; i < 32; i += 8)
        T[(size_t)(n0 + i) * K + k0 + tx] = __float2half_rn(t[tx][i]);
}

// ======================= attention middle ===================================
__global__ void colmax_part_kernel() {
    const int chunk = blockIdx.x;
    const int b = chunk / (NSEQ / 256);
    const int r0 = (chunk % (NSEQ / 256)) * 256;
    const int c = threadIdx.x;
    const __half* base = g_Kp + ((size_t)b * NSEQ + r0) * NC;
    float m = -INFINITY;
    for (int r = 0; r < 256; r++)
        m = fmaxf(m, __half2float(base[(size_t)r * NC + c]));
    g_partmax[(size_t)chunk * NC + c] = m;
}
__global__ void colmax_red_kernel() {
    const int b = blockIdx.x;
    const int c = threadIdx.x;
    float m = -INFINITY;
    for (int ch = 0; ch < NSEQ / 256; ch++)
        m = fmaxf(m, g_partmax[((size_t)(b * (NSEQ / 256) + ch)) * NC + c]);
    g_colmax[b * NC + c] = m;
}

#define CGRP 32
__global__ __launch_bounds__(256)
void ctx_part_kernel() {
    const int s  = blockIdx.x;
    const int bh = blockIdx.y;
    const int b = bh / NHEADS;
    const int h = bh % NHEADS;
    const int t = threadIdx.x;
    const int chunk = NSEQ / NSPLIT;
    __shared__ float ek[CGRP][DH];
    __shared__ float vv[CGRP][DH];
    const int e  = t & 31;
    const int d0 = (t >> 5) * 4;
    float acc0 = 0.f, acc1 = 0.f, acc2 = 0.f, acc3 = 0.f, zacc = 0.f;
    for (int g = 0; g < chunk / CGRP; g++) {
        #pragma unroll
        for (int i = 0; i < CGRP * 2 * DH / 256; i++) {
            int idx = t + i * 256;
            int row = idx >> 6;
            int col = idx & 63;
            int n = s * chunk + g * CGRP + row;
            size_t base = ((size_t)b * NSEQ + n) * NC + h * DH;
            if (col < DH) {
                float kv = __half2float(g_Kp[base + col]);
                ek[row][col] = expf(kv - g_colmax[b * NC + h * DH + col]);
            } else {
                vv[row][col - DH] = __half2float(g_Vp[base + (col - DH)]);
            }
        }
        __syncthreads();
        #pragma unroll 8
        for (int row = 0; row < CGRP; row++) {
            float v = vv[row][e];
            acc0 = fmaf(ek[row][d0 + 0], v, acc0);
            acc1 = fmaf(ek[row][d0 + 1], v, acc1);
            acc2 = fmaf(ek[row][d0 + 2], v, acc2);
            acc3 = fmaf(ek[row][d0 + 3], v, acc3);
        }
        if (t < DH) {
            #pragma unroll 8
            for (int row = 0; row < CGRP; row++) zacc += ek[row][t];
        }
        __syncthreads();
    }
    const size_t sp = ((size_t)bh * NSPLIT + s) * (DH * DH);
    g_Spart[sp + (d0 + 0) * DH + e] = acc0;
    g_Spart[sp + (d0 + 1) * DH + e] = acc1;
    g_Spart[sp + (d0 + 2) * DH + e] = acc2;
    g_Spart[sp + (d0 + 3) * DH + e] = acc3;
    if (t < DH) g_Zpart[((size_t)bh * NSPLIT + s) * DH + t] = zacc;
}
__global__ void ctx_reduce_kernel() {
    const int bh = blockIdx.x;
    const int t = threadIdx.x;
    const int d = t >> 5;
    __shared__ float zs[DH];
    float ssum = 0.f;
    for (int p = 0; p < NSPLIT; p++)
        ssum += g_Spart[((size_t)bh * NSPLIT + p) * (DH * DH) + t];
    if (t < DH) {
        float z = 0.f;
        for (int p = 0; p < NSPLIT; p++)
            z += g_Zpart[((size_t)bh * NSPLIT + p) * DH + t];
        zs[t] = z;
    }
    __syncthreads();
    g_ctx[(size_t)bh * (DH * DH) + t] = ssum / zs[d];
}

// fused softmax(Q) -> attn -> +residual -> LN1; two-phase, 1 barrier/block
#define ROWS_PER_BLK 16
__global__ __launch_bounds__(256)
void attn_ln1_kernel(const float* __restrict__ gamma,
                     const float* __restrict__ beta) {
    __shared__ float ys[ROWS_PER_BLK][NC];
    __shared__ float gb[2][NC];
    const int t = threadIdx.x;
    const int h = t >> 5;
    const int lane = t & 31;
    const int row0 = blockIdx.x * ROWS_PER_BLK;
    const int b = row0 / NSEQ;

    float ctx[DH];
    const float* cb = g_ctx + ((size_t)b * NHEADS + h) * DH * DH;
    #pragma unroll
    for (int d = 0; d < DH; d++) ctx[d] = cb[d * DH + lane];
    gb[0][t] = gamma[t];
    gb[1][t] = beta[t];

    for (int r = 0; r < ROWS_PER_BLK; r++) {
        const size_t off = (size_t)(row0 + r) * NC;
        float qv = __half2float(g_Qp[off + t]);
        float m = qv;
        #pragma unroll
        for (int s = 16; s > 0; s >>= 1) m = fmaxf(m, __shfl_xor_sync(0xffffffffu, m, s));
        float ev = expf(qv - m);
        float ss = ev;
        #pragma unroll
        for (int s = 16; s > 0; s >>= 1) ss += __shfl_xor_sync(0xffffffffu, ss, s);
        float qn = ev / ss;
        float acc = 0.f;
        #pragma unroll
        for (int d = 0; d < DH; d++) {
            float qd = __shfl_sync(0xffffffffu, qn, d);
            acc = fmaf(qd, ctx[d], acc);
        }
        ys[r][t] = __half2float(g_qh[off + t]) + acc;
    }
    __syncthreads();

    #pragma unroll
    for (int rr = 0; rr < ROWS_PER_BLK / 8; rr++) {
        const int r = h * (ROWS_PER_BLK / 8) + rr;
        float v[8], s1 = 0.f, s2 = 0.f;
        #pragma unroll
        for (int j = 0; j < 8; j++) {
            v[j] = ys[r][lane + 32 * j];
            s1 += v[j];
            s2 += v[j] * v[j];
        }
        #pragma unroll
        for (int s = 16; s > 0; s >>= 1) {
            s1 += __shfl_xor_sync(0xffffffffu, s1, s);
            s2 += __shfl_xor_sync(0xffffffffu, s2, s);
        }
        const float mean = s1 * (1.0f / NC);
        const float var  = s2 * (1.0f / NC) - mean * mean;
        const float rs   = rsqrtf(var + LN_EPS);
        const size_t off = (size_t)(row0 + r) * NC;
        #pragma unroll
        for (int j = 0; j < 8; j++) {
            const int c = lane + 32 * j;
            float xv = (v[j] - mean) * rs * gb[0][c] + gb[1][c];
            g_xh[off + c] = __float2half_rn(xv);
        }
    }
}

// ln2 warp-per-row: 8 rows/block, warp-local reductions, no block barriers
__global__ __launch_bounds__(256)
void ln2_kernel(const float* __restrict__ gamma, const float* __restrict__ beta,
                float* __restrict__ out) {
    const int t = threadIdx.x;
    const int h = t >> 5;
    const int lane = t & 31;
    const size_t row = (size_t)blockIdx.x * 8 + h;
    const size_t off = row * NC;
    float v[8], s1 = 0.f, s2 = 0.f;
    #pragma unroll
    for (int j = 0; j < 8; j++) {
        const int c = lane + 32 * j;
        v[j] = __half2float(g_xh[off + c]) + __half2float(g_ffout[off + c]);
        s1 += v[j];
        s2 += v[j] * v[j];
    }
    #pragma unroll
    for (int s = 16; s > 0; s >>= 1) {
        s1 += __shfl_xor_sync(0xffffffffu, s1, s);
        s2 += __shfl_xor_sync(0xffffffffu, s2, s);
    }
    const float mean = s1 * (1.0f / NC);
    const float var  = s2 * (1.0f / NC) - mean * mean;
    const float rs   = rsqrtf(var + LN_EPS);
    #pragma unroll
    for (int j = 0; j < 8; j++) {
        const int c = lane + 32 * j;
        out[off + c] = (v[j] - mean) * rs * gamma[c] + beta[c];
    }
}

// ======================= launch =============================================
extern "C" void kernel_launch(void* const* d_in, const int* in_sizes, int n_in,
                              void* d_out, int out_size) {
    const float* q     = (const float*)d_in[0];
    const float* kv    = (const float*)d_in[1];
    const float* wq_w  = (const float*)d_in[2];
    const float* wq_b  = (const float*)d_in[3];
    const float* wk_w  = (const float*)d_in[4];
    const float* wk_b  = (const float*)d_in[5];
    const float* wv_w  = (const float*)d_in[6];
    const float* wv_b  = (const float*)d_in[7];
    const float* ln1_g = (const float*)d_in[8];
    const float* ln1_b = (const float*)d_in[9];
    const float* ff1_w = (const float*)d_in[10];
    const float* ff1_b = (const float*)d_in[11];
    const float* ff2_w = (const float*)d_in[12];
    const float* ff2_b = (const float*)d_in[13];
    const float* ln2_g = (const float*)d_in[14];
    const float* ln2_b = (const float*)d_in[15];
    float* out = (float*)d_out;

    void *pQ, *pK, *pV, *pF;
    void *pqh, *pkvh, *pxh, *phh;
    void *wq, *wkv, *f1, *f2;
    cudaGetSymbolAddress(&pQ, g_Qp);    cudaGetSymbolAddress(&pK, g_Kp);
    cudaGetSymbolAddress(&pV, g_Vp);    cudaGetSymbolAddress(&pF, g_ffout);
    cudaGetSymbolAddress(&pqh, g_qh);   cudaGetSymbolAddress(&pkvh, g_kvh);
    cudaGetSymbolAddress(&pxh, g_xh);   cudaGetSymbolAddress(&phh, g_hh);
    cudaGetSymbolAddress(&wq, g_wqT);   cudaGetSymbolAddress(&wkv, g_wkvT);
    cudaGetSymbolAddress(&f1, g_f1T);   cudaGetSymbolAddress(&f2, g_f2T);

    cudaFuncSetAttribute(tc_gemm<0,0>, cudaFuncAttributeMaxDynamicSharedMemorySize, GEMM_SMEM);
    cudaFuncSetAttribute(tc_gemm<0,1>, cudaFuncAttributeMaxDynamicSharedMemorySize, GEMM_SMEM);
    cudaFuncSetAttribute(tc_gemm<1,0>, cudaFuncAttributeMaxDynamicSharedMemorySize, GEMM_SMEM);

    // one-time side-stream + events (created on first, uncaptured, call)
    static cudaStream_t sQ = nullptr;
    static cudaEvent_t evFork = nullptr, evQ = nullptr;
    if (!sQ) {
        cudaStreamCreateWithFlags(&sQ, cudaStreamNonBlocking);
        cudaEventCreateWithFlags(&evFork, cudaEventDisableTiming);
        cudaEventCreateWithFlags(&evQ, cudaEventDisableTiming);
    }

    const size_t n4 = (size_t)NROWS * NC / 4;
    conv_half2_kernel<<<(int)(2 * n4 / 256), 256>>>(q, (__half*)pqh, kv, (__half*)pkvh);
    dim3 tb(32, 8);
    convT_all_kernel<<<704, tb>>>(wq_w, wk_w, wv_w, ff1_w, ff2_w,
                                  (__half*)wq, (__half*)wkv,
                                  (__half*)wkv + 256 * NC,
                                  (__half*)f1, (__half*)f2);

    // fork: Q projection overlaps the whole K-side chain
    cudaEventRecord(evFork, 0);
    cudaStreamWaitEvent(sQ, evFork, 0);
    dim3 gQ(NC / 128, NROWS / 128);
    tc_gemm<0,0><<<gQ, 128, GEMM_SMEM, sQ>>>((__half*)pqh, (__half*)wq, wq_b, 0,
                                             (__half*)pQ, 0, NC, NC);
    cudaEventRecord(evQ, sQ);

    // main stream: K+V fused projection + colmax/ctx chain
    dim3 gKV(512 / 128, NROWS / 128);
    tc_gemm<0,1><<<gKV, 128, GEMM_SMEM>>>((__half*)pkvh, (__half*)wkv, wk_b, wv_b,
                                          (__half*)pK, (__half*)pV, 512, NC);
    colmax_part_kernel<<<BATCH * (NSEQ / 256), 256>>>();
    colmax_red_kernel<<<BATCH, 256>>>();
    ctx_part_kernel<<<dim3(NSPLIT, BATCH * NHEADS), 256>>>();
    ctx_reduce_kernel<<<BATCH * NHEADS, DH * DH>>>();

    // join: attn needs Q projection
    cudaStreamWaitEvent(0, evQ, 0);
    attn_ln1_kernel<<<NROWS / ROWS_PER_BLK, 256>>>(ln1_g, ln1_b);

    // FF
    dim3 gFF1(FFDIM / 128, NROWS / 128);
    tc_gemm<1,0><<<gFF1, 128, GEMM_SMEM>>>((__half*)pxh, (__half*)f1, ff1_b, 0,
                                           (__half*)phh, 0, FFDIM, NC);
    dim3 gFF2(NC / 128, NROWS / 128);
    tc_gemm<0,0><<<gFF2, 128, GEMM_SMEM>>>((__half*)phh, (__half*)f2, ff2_b, 0,
                                           (__half*)pF, 0, NC, FFDIM);

    ln2_kernel<<<NROWS / 8, 256>>>(ln2_g, ln2_b, out);
}